// round 10
// baseline (speedup 1.0000x reference)
#include <cuda_runtime.h>
#include <math.h>

#define B   16
#define C   512
#define T   1024
#define H   8
#define D   64

// ---------------- scratch (static device, no allocation) ----------------
__device__ float  g_q [B*H*T*D];   // [b,h,t,d]
__device__ float  g_k [B*H*T*D];   // [b,h,t,d]
__device__ float  g_v [B*H*T*D];   // [b,h,t,d]
__device__ float  g_ao[B*C*T];     // [b,c,t]
__device__ float2 g_rope[T*16];    // {cos,sin} per (t, pair)

// ---------------- tf32 helpers ----------------
__device__ __forceinline__ unsigned tf32(float f) {
    unsigned r; asm("cvt.rna.tf32.f32 %0, %1;" : "=r"(r) : "f"(f)); return r;
}
__device__ __forceinline__ void mma_tf32(float* c, const unsigned* a, const unsigned* b) {
    asm volatile(
        "mma.sync.aligned.m16n8k8.row.col.f32.tf32.tf32.f32 "
        "{%0,%1,%2,%3}, {%4,%5,%6,%7}, {%8,%9}, {%0,%1,%2,%3};\n"
        : "+f"(c[0]), "+f"(c[1]), "+f"(c[2]), "+f"(c[3])
        : "r"(a[0]), "r"(a[1]), "r"(a[2]), "r"(a[3]), "r"(b[0]), "r"(b[1]));
}
// pair-interleave within 8-groups: (0,4)(1,5)(2,6)(3,7) -> adjacent slots
__device__ __forceinline__ int ilv(int d) {
    return (d & ~7) | (((d & 3) << 1) | ((d & 7) >> 2));
}

// =====================================================================
// Kernel 1: QKV projection (tf32 tensor cores). Unchanged from R8.
// =====================================================================
__global__ __launch_bounds__(256) void qkv_gemm_tc(
    const float* __restrict__ x,
    const float* __restrict__ Wq, const float* __restrict__ bq,
    const float* __restrict__ Wk, const float* __restrict__ bk,
    const float* __restrict__ Wv, const float* __restrict__ bv)
{
    __shared__ unsigned As[128*36];   // W tile  [o][k], stride 36
    __shared__ unsigned Bs[32*132];   // x tile  [k][t], stride 132

    const int b  = blockIdx.z;
    const int w  = blockIdx.y >> 2;          // 0=q 1=k 2=v
    const int o0 = (blockIdx.y & 3) * 128;
    const int t0 = blockIdx.x * 128;

    const float* W    = (w == 0) ? Wq : (w == 1) ? Wk : Wv;
    const float* bias = (w == 0) ? bq : (w == 1) ? bk : bv;
    float*       outb = (w == 0) ? g_q : (w == 1) ? g_k : g_v;
    const float* Xb   = x + (size_t)b * C * T;

    const int tid  = threadIdx.x;
    const int lane = tid & 31, warp = tid >> 5;
    const int gid  = lane >> 2, tg = lane & 3;
    const int m0   = (warp >> 1) * 32;
    const int n0   = (warp & 1) * 64;

    const int ar0 = tid >> 3, ac = (tid & 7) * 4;
    const int br0 = tid >> 5, bc = (tid & 31) * 4;

    float acc[2][8][4];
    #pragma unroll
    for (int mf = 0; mf < 2; mf++)
        #pragma unroll
        for (int nf = 0; nf < 8; nf++)
            #pragma unroll
            for (int i = 0; i < 4; i++) acc[mf][nf][i] = 0.0f;

    for (int kk = 0; kk < C; kk += 32) {
        #pragma unroll
        for (int i = 0; i < 4; i++) {
            int r = ar0 + i * 32;
            float4 wv = *(const float4*)(W + (size_t)(o0 + r) * C + kk + ac);
            unsigned* p = &As[r * 36 + ac];
            p[0] = tf32(wv.x); p[1] = tf32(wv.y); p[2] = tf32(wv.z); p[3] = tf32(wv.w);
        }
        #pragma unroll
        for (int i = 0; i < 4; i++) {
            int r = br0 + i * 8;
            float4 xv = *(const float4*)(Xb + (size_t)(kk + r) * T + t0 + bc);
            unsigned* p = &Bs[r * 132 + bc];
            p[0] = tf32(xv.x); p[1] = tf32(xv.y); p[2] = tf32(xv.z); p[3] = tf32(xv.w);
        }
        __syncthreads();
        #pragma unroll
        for (int k8 = 0; k8 < 4; k8++) {
            const int kb = k8 * 8;
            unsigned a[2][4], bf[8][2];
            #pragma unroll
            for (int mf = 0; mf < 2; mf++) {
                int r = m0 + mf * 16 + gid;
                a[mf][0] = As[r * 36 + kb + tg];
                a[mf][1] = As[(r + 8) * 36 + kb + tg];
                a[mf][2] = As[r * 36 + kb + tg + 4];
                a[mf][3] = As[(r + 8) * 36 + kb + tg + 4];
            }
            #pragma unroll
            for (int nf = 0; nf < 8; nf++) {
                int cn = n0 + nf * 8 + gid;
                bf[nf][0] = Bs[(kb + tg) * 132 + cn];
                bf[nf][1] = Bs[(kb + tg + 4) * 132 + cn];
            }
            #pragma unroll
            for (int mf = 0; mf < 2; mf++)
                #pragma unroll
                for (int nf = 0; nf < 8; nf++)
                    mma_tf32(acc[mf][nf], a[mf], bf[nf]);
        }
        __syncthreads();
    }

    #pragma unroll
    for (int mf = 0; mf < 2; mf++) {
        int o1 = o0 + m0 + mf * 16 + gid;
        int o2 = o1 + 8;
        float bi1 = bias[o1], bi2 = bias[o2];
        float* p1 = outb + ((size_t)(b * H + (o1 >> 6)) * T) * D + (o1 & 63);
        float* p2 = outb + ((size_t)(b * H + (o2 >> 6)) * T) * D + (o2 & 63);
        #pragma unroll
        for (int nf = 0; nf < 8; nf++) {
            int t = t0 + n0 + nf * 8 + 2 * tg;
            p1[(size_t)t * D]       = acc[mf][nf][0] + bi1;
            p1[(size_t)(t + 1) * D] = acc[mf][nf][1] + bi1;
            p2[(size_t)t * D]       = acc[mf][nf][2] + bi2;
            p2[(size_t)(t + 1) * D] = acc[mf][nf][3] + bi2;
        }
    }
}

// =====================================================================
// Kernel 2a: RoPE table (fp64 once, tiny).  2b: apply (fp32, mem-bound).
// =====================================================================
__global__ void rope_table()
{
    const int idx = blockIdx.x * blockDim.x + threadIdx.x;  // 16384
    const int t = idx >> 4, i = idx & 15;
    double theta = exp(-(double)i * (9.210340371976184 / 16.0)); // ln(10000)/16
    double sd, cd;
    sincos((double)t * theta, &sd, &cd);
    g_rope[idx] = make_float2((float)cd, (float)sd);
}

__global__ __launch_bounds__(256) void rope_apply()
{
    const int idx = blockIdx.x * blockDim.x + threadIdx.x;  // 2*131072*4
    const int buf = idx >> 19;
    const int j   = idx & 524287;
    const int row = j >> 2;                 // [b,h,t] flattened
    const int qd  = j & 3;                  // pair quad 0..3
    const int t   = row & (T - 1);

    float* base = (buf ? g_k : g_q) + (size_t)row * D + qd * 4;
    float4 a  = *(const float4*)base;
    float4 bb = *(const float4*)(base + 16);
    const float4* tp = (const float4*)(g_rope + t * 16 + qd * 4);
    float4 t0v = tp[0], t1v = tp[1];   // {c0,s0,c1,s1},{c2,s2,c3,s3}

    float4 r0, r1;
    r0.x = a.x * t0v.x - bb.x * t0v.y;  r1.x = bb.x * t0v.x + a.x * t0v.y;
    r0.y = a.y * t0v.z - bb.y * t0v.w;  r1.y = bb.y * t0v.z + a.y * t0v.w;
    r0.z = a.z * t1v.x - bb.z * t1v.y;  r1.z = bb.z * t1v.x + a.z * t1v.y;
    r0.w = a.w * t1v.z - bb.w * t1v.w;  r1.w = bb.w * t1v.z + a.w * t1v.w;
    *(float4*)base        = r0;
    *(float4*)(base + 16) = r1;
}

// =====================================================================
// Kernel 3: flash attention v3 (tf32 mma.sync).
// CTA = (b, h, 128 q-rows); 4 warps, warp = 32 q-rows (2 mf of 16).
// Each B-fragment (K/V) load now feeds TWO mmas -> LDS traffic per unit
// work ~0.55x vs R8. 128 threads, 73.7KB smem -> 2 CTAs/SM.
// =====================================================================
#define QSTR 72

__global__ __launch_bounds__(128, 2) void attn_tc3()
{
    extern __shared__ unsigned sm_u[];
    unsigned* Qs = sm_u;               // [128][72] tf32, pre-scaled, d interleaved
    unsigned* Ks = Qs + 128 * QSTR;    // [64 key][72] tf32, d interleaved
    unsigned* Vt = Ks + 64 * QSTR;     // [64 d][72] tf32, key interleaved (transposed)
    float*    Sf = reinterpret_cast<float*>(Ks);  // epilogue staging [128][65]

    const int b = blockIdx.z, h = blockIdx.y, t0 = blockIdx.x * 128;
    const size_t bh = (size_t)(b * H + h);
    const float* Qg = g_q + bh * T * D;
    const float* Kg = g_k + bh * T * D;
    const float* Vg = g_v + bh * T * D;

    const int tid = threadIdx.x, lane = tid & 31, warp = tid >> 5;
    const int gid = lane >> 2, tg = lane & 3;
    const int m0  = warp * 32;                 // 32 q-rows per warp

    // ---- load Q tile (pre-scaled by 1/8, interleaved) ----
    #pragma unroll
    for (int j = 0; j < 16; j++) {
        int u = tid + j * 128;
        int r = u >> 4, c4 = (u & 15) << 2;
        float4 qv = *(const float4*)(Qg + (size_t)(t0 + r) * D + c4);
        unsigned* p = &Qs[r * QSTR];
        p[ilv(c4 + 0)] = tf32(0.125f * qv.x);
        p[ilv(c4 + 1)] = tf32(0.125f * qv.y);
        p[ilv(c4 + 2)] = tf32(0.125f * qv.z);
        p[ilv(c4 + 3)] = tf32(0.125f * qv.w);
    }

    float oacc[2][8][4];
    #pragma unroll
    for (int mf = 0; mf < 2; mf++)
        #pragma unroll
        for (int nf = 0; nf < 8; nf++)
            #pragma unroll
            for (int i = 0; i < 4; i++) oacc[mf][nf][i] = 0.0f;
    float mr[2][2] = {{-INFINITY, -INFINITY}, {-INFINITY, -INFINITY}};
    float lr[2][2] = {{0.0f, 0.0f}, {0.0f, 0.0f}};

    for (int kb = 0; kb < T / 64; kb++) {
        const int k0 = kb * 64;
        // ---- first half prefetch (overlaps peers' tail compute) ----
        float4 kr[4], vr[4];
        #pragma unroll
        for (int j = 0; j < 4; j++) {
            int u = tid + j * 128;
            kr[j] = *(const float4*)(Kg + (size_t)(k0 + (u >> 4)) * D + ((u & 15) << 2));
            vr[j] = *(const float4*)(Vg + (size_t)(k0 + (u & 63)) * D + ((u >> 6) << 2));
        }
        __syncthreads();   // everyone done with previous tile
        #pragma unroll
        for (int j = 0; j < 8; j++) {
            int u = tid + j * 128;
            float4 kv, vv;
            if (j < 4) { kv = kr[j]; vv = vr[j]; }
            else {
                kv = *(const float4*)(Kg + (size_t)(k0 + (u >> 4)) * D + ((u & 15) << 2));
                vv = *(const float4*)(Vg + (size_t)(k0 + (u & 63)) * D + ((u >> 6) << 2));
            }
            int r = u >> 4, c4 = (u & 15) << 2;
            unsigned* p = &Ks[r * QSTR];
            p[ilv(c4 + 0)] = tf32(kv.x);
            p[ilv(c4 + 1)] = tf32(kv.y);
            p[ilv(c4 + 2)] = tf32(kv.z);
            p[ilv(c4 + 3)] = tf32(kv.w);
            int rv = u & 63, cv = (u >> 6) << 2;
            int cr = ilv(rv);
            Vt[(cv + 0) * QSTR + cr] = tf32(vv.x);
            Vt[(cv + 1) * QSTR + cr] = tf32(vv.y);
            Vt[(cv + 2) * QSTR + cr] = tf32(vv.z);
            Vt[(cv + 3) * QSTR + cr] = tf32(vv.w);
        }
        __syncthreads();

        // ---- S = Q K^T  (2 mf tiles share every K fragment) ----
        float sacc[2][8][4];
        #pragma unroll
        for (int mf = 0; mf < 2; mf++)
            #pragma unroll
            for (int nf = 0; nf < 8; nf++)
                #pragma unroll
                for (int i = 0; i < 4; i++) sacc[mf][nf][i] = 0.0f;
        #pragma unroll
        for (int k8 = 0; k8 < 8; k8++) {
            const int kc = k8 * 8 + 2 * tg;
            uint2 qa0 = *(const uint2*)&Qs[(m0 + gid) * QSTR + kc];
            uint2 qa1 = *(const uint2*)&Qs[(m0 + gid + 8) * QSTR + kc];
            uint2 qb0 = *(const uint2*)&Qs[(m0 + 16 + gid) * QSTR + kc];
            uint2 qb1 = *(const uint2*)&Qs[(m0 + 24 + gid) * QSTR + kc];
            unsigned a0[4] = {qa0.x, qa1.x, qa0.y, qa1.y};
            unsigned a1[4] = {qb0.x, qb1.x, qb0.y, qb1.y};
            #pragma unroll
            for (int nf = 0; nf < 8; nf++) {
                uint2 kbv = *(const uint2*)&Ks[(nf * 8 + gid) * QSTR + kc];
                unsigned bbv[2] = {kbv.x, kbv.y};
                mma_tf32(sacc[0][nf], a0, bbv);
                mma_tf32(sacc[1][nf], a1, bbv);
            }
        }

        // ---- online softmax (quad reductions), exp in place ----
        #pragma unroll
        for (int mf = 0; mf < 2; mf++) {
            #pragma unroll
            for (int hf = 0; hf < 2; hf++) {
                float mx = -INFINITY;
                #pragma unroll
                for (int nf = 0; nf < 8; nf++)
                    mx = fmaxf(mx, fmaxf(sacc[mf][nf][hf * 2], sacc[mf][nf][hf * 2 + 1]));
                mx = fmaxf(mx, __shfl_xor_sync(0xffffffffu, mx, 1));
                mx = fmaxf(mx, __shfl_xor_sync(0xffffffffu, mx, 2));
                float mn = fmaxf(mr[mf][hf], mx);
                float al = __expf(mr[mf][hf] - mn);
                mr[mf][hf] = mn;
                float sum = 0.0f;
                #pragma unroll
                for (int nf = 0; nf < 8; nf++) {
                    float p0 = __expf(sacc[mf][nf][hf * 2] - mn);
                    float p1 = __expf(sacc[mf][nf][hf * 2 + 1] - mn);
                    sacc[mf][nf][hf * 2]     = p0;
                    sacc[mf][nf][hf * 2 + 1] = p1;
                    sum += p0 + p1;
                    oacc[mf][nf][hf * 2]     *= al;
                    oacc[mf][nf][hf * 2 + 1] *= al;
                }
                sum += __shfl_xor_sync(0xffffffffu, sum, 1);
                sum += __shfl_xor_sync(0xffffffffu, sum, 2);
                lr[mf][hf] = lr[mf][hf] * al + sum;
            }
        }

        // ---- O += P V  (2 mf tiles share every V fragment) ----
        const int sl0 = (lane & ~3) | (tg >> 1);
        const bool od = (tg & 1);
        #pragma unroll
        for (int k8 = 0; k8 < 8; k8++) {
            unsigned pa[2][4];
            #pragma unroll
            for (int mf = 0; mf < 2; mf++) {
                float v00 = __shfl_sync(0xffffffffu, sacc[mf][k8][0], sl0);
                float v01 = __shfl_sync(0xffffffffu, sacc[mf][k8][1], sl0);
                float v10 = __shfl_sync(0xffffffffu, sacc[mf][k8][2], sl0);
                float v11 = __shfl_sync(0xffffffffu, sacc[mf][k8][3], sl0);
                float v20 = __shfl_sync(0xffffffffu, sacc[mf][k8][0], sl0 + 2);
                float v21 = __shfl_sync(0xffffffffu, sacc[mf][k8][1], sl0 + 2);
                float v30 = __shfl_sync(0xffffffffu, sacc[mf][k8][2], sl0 + 2);
                float v31 = __shfl_sync(0xffffffffu, sacc[mf][k8][3], sl0 + 2);
                pa[mf][0] = tf32(od ? v01 : v00);
                pa[mf][1] = tf32(od ? v11 : v10);
                pa[mf][2] = tf32(od ? v21 : v20);
                pa[mf][3] = tf32(od ? v31 : v30);
            }
            const int kc = k8 * 8 + 2 * tg;
            #pragma unroll
            for (int nf = 0; nf < 8; nf++) {
                uint2 vb = *(const uint2*)&Vt[(nf * 8 + gid) * QSTR + kc];
                unsigned bbv[2] = {vb.x, vb.y};
                mma_tf32(oacc[0][nf], pa[0], bbv);
                mma_tf32(oacc[1][nf], pa[1], bbv);
            }
        }
    }

    // ---- epilogue: normalize, stage (stride 65), transposed write ----
    __syncthreads();
    #pragma unroll
    for (int mf = 0; mf < 2; mf++) {
        const float inv0 = 1.0f / lr[mf][0], inv1 = 1.0f / lr[mf][1];
        const int r0 = m0 + mf * 16 + gid;
        #pragma unroll
        for (int nf = 0; nf < 8; nf++) {
            int cc = nf * 8 + 2 * tg;
            Sf[r0 * 65 + cc]           = oacc[mf][nf][0] * inv0;
            Sf[r0 * 65 + cc + 1]       = oacc[mf][nf][1] * inv0;
            Sf[(r0 + 8) * 65 + cc]     = oacc[mf][nf][2] * inv1;
            Sf[(r0 + 8) * 65 + cc + 1] = oacc[mf][nf][3] * inv1;
        }
    }
    __syncthreads();
    float* Og = g_ao + bh * (size_t)D * T;
    #pragma unroll
    for (int j = 0; j < 64; j++) {
        int u = tid + j * 128;
        int dd = u >> 7, r = u & 127;
        Og[(size_t)dd * T + t0 + r] = Sf[r * 65 + dd];
    }
}

// =====================================================================
// Kernel 4: output projection (tf32 tensor cores). Unchanged from R8.
// =====================================================================
__global__ __launch_bounds__(256) void out_gemm_tc(
    const float* __restrict__ Wo, const float* __restrict__ bo,
    float* __restrict__ out)
{
    __shared__ unsigned As[128*36];   // Wo tile [o][k]
    __shared__ unsigned Bs[32*132];   // ao tile [k][t]

    const int b  = blockIdx.z;
    const int o0 = blockIdx.y * 128;
    const int t0 = blockIdx.x * 128;
    const float* Xb = g_ao + (size_t)b * C * T;

    const int tid  = threadIdx.x;
    const int lane = tid & 31, warp = tid >> 5;
    const int gid  = lane >> 2, tg = lane & 3;
    const int m0   = (warp >> 1) * 32;
    const int n0   = (warp & 1) * 64;

    const int ar0 = tid >> 3, ac = (tid & 7) * 4;
    const int br0 = tid >> 5, bc = (tid & 31) * 4;

    float acc[2][8][4];
    #pragma unroll
    for (int mf = 0; mf < 2; mf++)
        #pragma unroll
        for (int nf = 0; nf < 8; nf++)
            #pragma unroll
            for (int i = 0; i < 4; i++) acc[mf][nf][i] = 0.0f;

    for (int kk = 0; kk < C; kk += 32) {
        #pragma unroll
        for (int i = 0; i < 4; i++) {
            int r = ar0 + i * 32;
            float4 wv = *(const float4*)(Wo + (size_t)(o0 + r) * C + kk + ac);
            unsigned* p = &As[r * 36 + ac];
            p[0] = tf32(wv.x); p[1] = tf32(wv.y); p[2] = tf32(wv.z); p[3] = tf32(wv.w);
        }
        #pragma unroll
        for (int i = 0; i < 4; i++) {
            int r = br0 + i * 8;
            float4 xv = *(const float4*)(Xb + (size_t)(kk + r) * T + t0 + bc);
            unsigned* p = &Bs[r * 132 + bc];
            p[0] = tf32(xv.x); p[1] = tf32(xv.y); p[2] = tf32(xv.z); p[3] = tf32(xv.w);
        }
        __syncthreads();
        #pragma unroll
        for (int k8 = 0; k8 < 4; k8++) {
            const int kb = k8 * 8;
            unsigned a[2][4], bf[8][2];
            #pragma unroll
            for (int mf = 0; mf < 2; mf++) {
                int r = m0 + mf * 16 + gid;
                a[mf][0] = As[r * 36 + kb + tg];
                a[mf][1] = As[(r + 8) * 36 + kb + tg];
                a[mf][2] = As[r * 36 + kb + tg + 4];
                a[mf][3] = As[(r + 8) * 36 + kb + tg + 4];
            }
            #pragma unroll
            for (int nf = 0; nf < 8; nf++) {
                int cn = n0 + nf * 8 + gid;
                bf[nf][0] = Bs[(kb + tg) * 132 + cn];
                bf[nf][1] = Bs[(kb + tg + 4) * 132 + cn];
            }
            #pragma unroll
            for (int mf = 0; mf < 2; mf++)
                #pragma unroll
                for (int nf = 0; nf < 8; nf++)
                    mma_tf32(acc[mf][nf], a[mf], bf[nf]);
        }
        __syncthreads();
    }

    #pragma unroll
    for (int mf = 0; mf < 2; mf++) {
        int o1 = o0 + m0 + mf * 16 + gid;
        int o2 = o1 + 8;
        float bi1 = bo[o1], bi2 = bo[o2];
        float* p1 = out + (size_t)b * C * T + (size_t)o1 * T;
        float* p2 = out + (size_t)b * C * T + (size_t)o2 * T;
        #pragma unroll
        for (int nf = 0; nf < 8; nf++) {
            int t = t0 + n0 + nf * 8 + 2 * tg;
            float2 v1 = make_float2(acc[mf][nf][0] + bi1, acc[mf][nf][1] + bi1);
            float2 v2 = make_float2(acc[mf][nf][2] + bi2, acc[mf][nf][3] + bi2);
            *(float2*)(p1 + t) = v1;
            *(float2*)(p2 + t) = v2;
        }
    }
}

// =====================================================================
extern "C" void kernel_launch(void* const* d_in, const int* in_sizes, int n_in,
                              void* d_out, int out_size)
{
    const float* x  = (const float*)d_in[0];
    const float* Wq = (const float*)d_in[1];
    const float* bq = (const float*)d_in[2];
    const float* Wk = (const float*)d_in[3];
    const float* bk = (const float*)d_in[4];
    const float* Wv = (const float*)d_in[5];
    const float* bv = (const float*)d_in[6];
    const float* Wo = (const float*)d_in[7];
    const float* bo = (const float*)d_in[8];
    float* out = (float*)d_out;

    const int attn_smem = (128 + 64 + 64) * QSTR * (int)sizeof(unsigned); // 73728 B
    cudaFuncSetAttribute(attn_tc3,
                         cudaFuncAttributeMaxDynamicSharedMemorySize, attn_smem);

    qkv_gemm_tc<<<dim3(T / 128, 12, B), 256>>>(x, Wq, bq, Wk, bk, Wv, bv);
    rope_table<<<64, 256>>>();
    rope_apply<<<(2 * B * H * T * 4) / 256, 256>>>();
    attn_tc3<<<dim3(T / 128, H, B), 128, attn_smem>>>();
    out_gemm_tc<<<dim3(T / 128, C / 128, B), 256>>>(Wo, bo, out);
}